// round 12
// baseline (speedup 1.0000x reference)
#include <cuda_runtime.h>
#include <cstdint>

#define B_DIM 16
#define T_DIM 8
#define C_DIM 64
#define P_DIM 2048
#define ROWS  (B_DIM * T_DIM * C_DIM)     // 8192 destination rows
#define TOTAL_ELEMS (ROWS * P_DIM)        // 16777216
#define NTHR 512                          // one float4 per thread -> small live set
#define ROW_BYTES (P_DIM * 4)             // 8192 bytes per row

// Block partials (float4 per destination row). No device-side allocation.
__device__ float4 g_part[ROWS];

__device__ __forceinline__ uint32_t smem_u32(const void* p) {
    uint32_t a;
    asm("{ .reg .u64 t; cvta.to.shared.u64 t, %1; cvt.u32.u64 %0, t; }"
        : "=r"(a) : "l"(p));
    return a;
}

// One CTA per destination row, 512 threads, one float4/thread.
// Batched loads (max MLP) with a ~48-reg live set -> 4 CTAs/SM (64 warps)
// vs R6's 3 CTAs/SM at 24 warps. TMA fills the three source rows.
__global__ __launch_bounds__(NTHR) void attnloss_partial_kernel(
    const float* __restrict__ x,
    const float* __restrict__ attn,
    const float* __restrict__ noise,
    const int* __restrict__ mask,    // bool promoted to 4-byte words
    const int* __restrict__ pB1, const int* __restrict__ pT1,
    const int* __restrict__ pC1, const int* __restrict__ pP1,
    const int* __restrict__ pB2, const int* __restrict__ pT2,
    const int* __restrict__ pC2, const int* __restrict__ pP2,
    const int* __restrict__ pB3, const int* __restrict__ pT3,
    const int* __restrict__ pC3, const int* __restrict__ pP3)
{
    __shared__ __align__(128) float sm[3 * P_DIM];   // 24 KB: three source rows
    __shared__ __align__(8) uint64_t mbar;

    const float* const sm1 = sm;
    const float* const sm2 = sm + P_DIM;
    const float* const sm3 = sm + 2 * P_DIM;

    const int tid = threadIdx.x;
    const int blk = blockIdx.x;              // destination row id
    const uint32_t mbar_a = smem_u32(&mbar);

    if (tid == 0) {
        asm volatile("mbarrier.init.shared.b64 [%0], 1;" :: "r"(mbar_a) : "memory");
    }
    __syncthreads();

    if (tid == 0) {
        const int c = blk & (C_DIM - 1);
        const int t = (blk >> 6) & (T_DIM - 1);
        const int b = blk >> 9;
        // Source row bases (contiguous 8 KB rows of x). 32-bit math: max < 2^24.
        const int rb1 = ((((__ldg(pB1 + b) << 3) + __ldg(pT1 + t)) << 6) + __ldg(pC1 + c)) << 11;
        const int rb2 = ((((__ldg(pB2 + b) << 3) + __ldg(pT2 + t)) << 6) + __ldg(pC2 + c)) << 11;
        const int rb3 = ((((__ldg(pB3 + b) << 3) + __ldg(pT3 + t)) << 6) + __ldg(pC3 + c)) << 11;

        asm volatile("mbarrier.arrive.expect_tx.shared.b64 _, [%0], %1;"
                     :: "r"(mbar_a), "r"(3 * ROW_BYTES) : "memory");
        asm volatile("cp.async.bulk.shared::cta.global.mbarrier::complete_tx::bytes [%0], [%1], %2, [%3];"
                     :: "r"(smem_u32(sm1)), "l"(x + rb1), "r"(ROW_BYTES), "r"(mbar_a) : "memory");
        asm volatile("cp.async.bulk.shared::cta.global.mbarrier::complete_tx::bytes [%0], [%1], %2, [%3];"
                     :: "r"(smem_u32(sm2)), "l"(x + rb2), "r"(ROW_BYTES), "r"(mbar_a) : "memory");
        asm volatile("cp.async.bulk.shared::cta.global.mbarrier::complete_tx::bytes [%0], [%1], %2, [%3];"
                     :: "r"(smem_u32(sm3)), "l"(x + rb3), "r"(ROW_BYTES), "r"(mbar_a) : "memory");
    }

    // Batch ALL streaming loads up front (max MLP, in flight across the wait).
    const int gv = (blk << 9) + tid;                      // global float4 index
    const float4 x4 = __ldg((const float4*)x + gv);       // L2-resident
    const float4 a4 = __ldcs((const float4*)attn + gv);   // stream
    const float4 n4 = __ldcs((const float4*)noise + gv);  // stream
    const int4  m4 = __ldcs((const int4*)mask + gv);      // stream
    const int4 pp1 = __ldg((const int4*)pP1 + tid);       // L1-hot tables
    const int4 pp2 = __ldg((const int4*)pP2 + tid);
    const int4 pp3 = __ldg((const int4*)pP3 + tid);

    // Wait for the three source rows (acquire orders the LDS gathers below).
    {
        uint32_t done;
        asm volatile(
            "{\n\t.reg .pred p;\n\t"
            "mbarrier.try_wait.parity.acquire.cta.shared::cta.b64 p, [%1], 0;\n\t"
            "selp.b32 %0, 1, 0, p;\n\t}"
            : "=r"(done) : "r"(mbar_a) : "memory");
        if (!done) {
            asm volatile(
                "{\n\t.reg .pred P1;\n\t"
                "WAIT_LOOP_%=:\n\t"
                "mbarrier.try_wait.parity.acquire.cta.shared::cta.b64 P1, [%0], 0, 0x989680;\n\t"
                "@P1 bra.uni WAIT_DONE_%=;\n\t"
                "bra.uni WAIT_LOOP_%=;\n\t"
                "WAIT_DONE_%=:\n\t}"
                :: "r"(mbar_a) : "memory");
        }
    }

    float s0, s1a = 0.f, s2a = 0.f, s3a = 0.f;

    s0 = (m4.x ? a4.x * n4.x * n4.x : 0.f)
       + (m4.y ? a4.y * n4.y * n4.y : 0.f)
       + (m4.z ? a4.z * n4.z * n4.z : 0.f)
       + (m4.w ? a4.w * n4.w * n4.w : 0.f);

    float d;
    d = x4.x - sm1[pp1.x]; s1a += a4.x * d * d;
    d = x4.y - sm1[pp1.y]; s1a += a4.y * d * d;
    d = x4.z - sm1[pp1.z]; s1a += a4.z * d * d;
    d = x4.w - sm1[pp1.w]; s1a += a4.w * d * d;

    d = x4.x - sm2[pp2.x]; s2a += a4.x * d * d;
    d = x4.y - sm2[pp2.y]; s2a += a4.y * d * d;
    d = x4.z - sm2[pp2.z]; s2a += a4.z * d * d;
    d = x4.w - sm2[pp2.w]; s2a += a4.w * d * d;

    d = x4.x - sm3[pp3.x]; s3a += a4.x * d * d;
    d = x4.y - sm3[pp3.y]; s3a += a4.y * d * d;
    d = x4.z - sm3[pp3.z]; s3a += a4.z * d * d;
    d = x4.w - sm3[pp3.w]; s3a += a4.w * d * d;

    // Block reduction (deterministic tree)
    #pragma unroll
    for (int o = 16; o > 0; o >>= 1) {
        s0  += __shfl_down_sync(0xffffffffu, s0,  o);
        s1a += __shfl_down_sync(0xffffffffu, s1a, o);
        s2a += __shfl_down_sync(0xffffffffu, s2a, o);
        s3a += __shfl_down_sync(0xffffffffu, s3a, o);
    }
    __shared__ float4 shp[NTHR / 32];
    const int w = tid >> 5;
    if ((tid & 31) == 0) shp[w] = make_float4(s0, s1a, s2a, s3a);
    __syncthreads();

    if (tid == 0) {
        float4 acc = shp[0];
        #pragma unroll
        for (int k = 1; k < NTHR / 32; k++) {
            acc.x += shp[k].x; acc.y += shp[k].y;
            acc.z += shp[k].z; acc.w += shp[k].w;
        }
        g_part[blk] = acc;
    }
}

#define FTHR 1024

__global__ __launch_bounds__(FTHR) void attnloss_final_kernel(float* __restrict__ out)
{
    float4 acc = make_float4(0.f, 0.f, 0.f, 0.f);
    #pragma unroll
    for (int u = 0; u < ROWS / FTHR; u++) {
        const float4 p = g_part[u * FTHR + threadIdx.x];
        acc.x += p.x; acc.y += p.y; acc.z += p.z; acc.w += p.w;
    }
    #pragma unroll
    for (int o = 16; o > 0; o >>= 1) {
        acc.x += __shfl_down_sync(0xffffffffu, acc.x, o);
        acc.y += __shfl_down_sync(0xffffffffu, acc.y, o);
        acc.z += __shfl_down_sync(0xffffffffu, acc.z, o);
        acc.w += __shfl_down_sync(0xffffffffu, acc.w, o);
    }
    __shared__ float4 shp[FTHR / 32];
    const int w = threadIdx.x >> 5;
    if ((threadIdx.x & 31) == 0) shp[w] = acc;
    __syncthreads();

    if (threadIdx.x == 0) {
        float4 r = shp[0];
        #pragma unroll
        for (int k = 1; k < FTHR / 32; k++) {
            r.x += shp[k].x; r.y += shp[k].y;
            r.z += shp[k].z; r.w += shp[k].w;
        }
        const float inv = 1.0f / (float)TOTAL_ELEMS;
        const float pos = r.x * inv;
        const float n1  = r.y * inv;
        const float n2  = r.z * inv;
        const float n3  = r.w * inv;
        // TEMP = 1:  loss = -pos + log(exp(n1)+exp(n2)+exp(n3))
        out[0] = -pos + logf(expf(n1) + expf(n2) + expf(n3));
    }
}

extern "C" void kernel_launch(void* const* d_in, const int* in_sizes, int n_in,
                              void* d_out, int out_size)
{
    const float* x     = (const float*)d_in[0];
    const float* attn  = (const float*)d_in[1];
    const float* noise = (const float*)d_in[2];
    const int*   mask  = (const int*)d_in[3];
    const int* pB1 = (const int*)d_in[4];
    const int* pT1 = (const int*)d_in[5];
    const int* pC1 = (const int*)d_in[6];
    const int* pP1 = (const int*)d_in[7];
    const int* pB2 = (const int*)d_in[8];
    const int* pT2 = (const int*)d_in[9];
    const int* pC2 = (const int*)d_in[10];
    const int* pP2 = (const int*)d_in[11];
    const int* pB3 = (const int*)d_in[12];
    const int* pT3 = (const int*)d_in[13];
    const int* pC3 = (const int*)d_in[14];
    const int* pP3 = (const int*)d_in[15];

    attnloss_partial_kernel<<<ROWS, NTHR>>>(
        x, attn, noise, mask,
        pB1, pT1, pC1, pP1,
        pB2, pT2, pC2, pP2,
        pB3, pT3, pC3, pP3);
    attnloss_final_kernel<<<1, FTHR>>>((float*)d_out);
}

// round 13
// speedup vs baseline: 1.0339x; 1.0339x over previous
#include <cuda_runtime.h>
#include <cstdint>

#define B_DIM 16
#define T_DIM 8
#define C_DIM 64
#define P_DIM 2048
#define ROWS  (B_DIM * T_DIM * C_DIM)     // 8192 destination rows
#define TOTAL_ELEMS (ROWS * P_DIM)        // 16777216
#define NTHR 256
#define NCTA (ROWS / 2)                   // 4096 CTAs, two rows each
#define ROW_BYTES (P_DIM * 4)             // 8192 bytes per row

// SMEM layout (dynamic): [0:16) mbarA/mbarB | [16:144) shp | [256:+48K) buffers
#define SM_OFF_MBAR 0
#define SM_OFF_SHP  16
#define SM_OFF_BUF  256
#define SMEM_TOTAL  (SM_OFF_BUF + 6 * ROW_BYTES)

// Per-CTA partials. No device-side allocation.
__device__ float4 g_part[NCTA];

__device__ __forceinline__ uint32_t smem_u32(const void* p) {
    uint32_t a;
    asm("{ .reg .u64 t; cvta.to.shared.u64 t, %1; cvt.u32.u64 %0, t; }"
        : "=r"(a) : "l"(p));
    return a;
}

__device__ __forceinline__ void mbar_wait0(uint32_t mbar_a) {
    uint32_t done;
    asm volatile(
        "{\n\t.reg .pred p;\n\t"
        "mbarrier.try_wait.parity.acquire.cta.shared::cta.b64 p, [%1], 0;\n\t"
        "selp.b32 %0, 1, 0, p;\n\t}"
        : "=r"(done) : "r"(mbar_a) : "memory");
    if (!done) {
        asm volatile(
            "{\n\t.reg .pred P1;\n\t"
            "WAIT_LOOP_%=:\n\t"
            "mbarrier.try_wait.parity.acquire.cta.shared::cta.b64 P1, [%0], 0, 0x989680;\n\t"
            "@P1 bra.uni WAIT_DONE_%=;\n\t"
            "bra.uni WAIT_LOOP_%=;\n\t"
            "WAIT_DONE_%=:\n\t}"
            :: "r"(mbar_a) : "memory");
    }
}

// Two destination rows per CTA. Both row-triples' TMA copies are issued up
// front; row B's TMA latency hides under row A's stream loads + compute.
// Batched operand loads per row (R6's winning pattern, ~80 regs, 3 CTAs/SM).
__global__ __launch_bounds__(NTHR) void attnloss_partial_kernel(
    const float* __restrict__ x,
    const float* __restrict__ attn,
    const float* __restrict__ noise,
    const int* __restrict__ mask,    // bool promoted to 4-byte words
    const int* __restrict__ pB1, const int* __restrict__ pT1,
    const int* __restrict__ pC1, const int* __restrict__ pP1,
    const int* __restrict__ pB2, const int* __restrict__ pT2,
    const int* __restrict__ pC2, const int* __restrict__ pP2,
    const int* __restrict__ pB3, const int* __restrict__ pT3,
    const int* __restrict__ pC3, const int* __restrict__ pP3)
{
    extern __shared__ __align__(128) char smem[];
    float* const buf = (float*)(smem + SM_OFF_BUF);      // 6 rows: A(3) then B(3)
    float4* const shp = (float4*)(smem + SM_OFF_SHP);
    const uint32_t mbarA = smem_u32(smem + SM_OFF_MBAR);
    const uint32_t mbarB = mbarA + 8;

    const int tid = threadIdx.x;
    const int rA = blockIdx.x << 1;          // first destination row
    const int rB = rA + 1;

    if (tid == 0) {
        asm volatile("mbarrier.init.shared.b64 [%0], 1;" :: "r"(mbarA) : "memory");
        asm volatile("mbarrier.init.shared.b64 [%0], 1;" :: "r"(mbarB) : "memory");
    }
    __syncthreads();

    if (tid == 0) {
        // rA and rB share b,t (rB = rA+1 differs only in c's low bit).
        #pragma unroll
        for (int h = 0; h < 2; h++) {
            const int row = rA + h;
            const int c = row & (C_DIM - 1);
            const int t = (row >> 6) & (T_DIM - 1);
            const int b = row >> 9;
            const int rb1 = ((((__ldg(pB1 + b) << 3) + __ldg(pT1 + t)) << 6) + __ldg(pC1 + c)) << 11;
            const int rb2 = ((((__ldg(pB2 + b) << 3) + __ldg(pT2 + t)) << 6) + __ldg(pC2 + c)) << 11;
            const int rb3 = ((((__ldg(pB3 + b) << 3) + __ldg(pT3 + t)) << 6) + __ldg(pC3 + c)) << 11;
            const uint32_t mb = h ? mbarB : mbarA;
            const uint32_t d  = smem_u32(buf + h * (3 * P_DIM));
            asm volatile("mbarrier.arrive.expect_tx.shared.b64 _, [%0], %1;"
                         :: "r"(mb), "r"(3 * ROW_BYTES) : "memory");
            asm volatile("cp.async.bulk.shared::cta.global.mbarrier::complete_tx::bytes [%0], [%1], %2, [%3];"
                         :: "r"(d), "l"(x + rb1), "r"(ROW_BYTES), "r"(mb) : "memory");
            asm volatile("cp.async.bulk.shared::cta.global.mbarrier::complete_tx::bytes [%0], [%1], %2, [%3];"
                         :: "r"(d + ROW_BYTES), "l"(x + rb2), "r"(ROW_BYTES), "r"(mb) : "memory");
            asm volatile("cp.async.bulk.shared::cta.global.mbarrier::complete_tx::bytes [%0], [%1], %2, [%3];"
                         :: "r"(d + 2 * ROW_BYTES), "l"(x + rb3), "r"(ROW_BYTES), "r"(mb) : "memory");
        }
    }

    float s0 = 0.f, s1a = 0.f, s2a = 0.f, s3a = 0.f;

    #pragma unroll
    for (int h = 0; h < 2; h++) {
        const int row = rA + h;
        const float* const sm1 = buf + h * (3 * P_DIM);
        const float* const sm2 = sm1 + P_DIM;
        const float* const sm3 = sm2 + P_DIM;

        // Batch ALL of this row's loads up front (max MLP, R6 pattern).
        float4 x4[2], a4[2], n4[2];
        int4 m4[2], pp1[2], pp2[2], pp3[2];
        #pragma unroll
        for (int j = 0; j < 2; j++) {
            const int vloc = j * NTHR + tid;         // 0..511, warp-contiguous
            const int gv = (row << 9) + vloc;
            x4[j] = __ldg((const float4*)x + gv);            // L2-resident
            a4[j] = __ldcs((const float4*)attn + gv);        // stream
            n4[j] = __ldcs((const float4*)noise + gv);       // stream
            m4[j] = __ldcs((const int4*)mask + gv);          // stream
            pp1[j] = __ldg((const int4*)pP1 + vloc);         // L1-hot tables
            pp2[j] = __ldg((const int4*)pP2 + vloc);
            pp3[j] = __ldg((const int4*)pP3 + vloc);
        }

        // Wait for this row's source triple.
        mbar_wait0(h ? mbarB : mbarA);

        #pragma unroll
        for (int j = 0; j < 2; j++) {
            s0 += (m4[j].x ? a4[j].x * n4[j].x * n4[j].x : 0.f)
                + (m4[j].y ? a4[j].y * n4[j].y * n4[j].y : 0.f)
                + (m4[j].z ? a4[j].z * n4[j].z * n4[j].z : 0.f)
                + (m4[j].w ? a4[j].w * n4[j].w * n4[j].w : 0.f);

            float d;
            d = x4[j].x - sm1[pp1[j].x]; s1a += a4[j].x * d * d;
            d = x4[j].y - sm1[pp1[j].y]; s1a += a4[j].y * d * d;
            d = x4[j].z - sm1[pp1[j].z]; s1a += a4[j].z * d * d;
            d = x4[j].w - sm1[pp1[j].w]; s1a += a4[j].w * d * d;

            d = x4[j].x - sm2[pp2[j].x]; s2a += a4[j].x * d * d;
            d = x4[j].y - sm2[pp2[j].y]; s2a += a4[j].y * d * d;
            d = x4[j].z - sm2[pp2[j].z]; s2a += a4[j].z * d * d;
            d = x4[j].w - sm2[pp2[j].w]; s2a += a4[j].w * d * d;

            d = x4[j].x - sm3[pp3[j].x]; s3a += a4[j].x * d * d;
            d = x4[j].y - sm3[pp3[j].y]; s3a += a4[j].y * d * d;
            d = x4[j].z - sm3[pp3[j].z]; s3a += a4[j].z * d * d;
            d = x4[j].w - sm3[pp3[j].w]; s3a += a4[j].w * d * d;
        }
    }

    // One block reduction per CTA (deterministic tree).
    #pragma unroll
    for (int o = 16; o > 0; o >>= 1) {
        s0  += __shfl_down_sync(0xffffffffu, s0,  o);
        s1a += __shfl_down_sync(0xffffffffu, s1a, o);
        s2a += __shfl_down_sync(0xffffffffu, s2a, o);
        s3a += __shfl_down_sync(0xffffffffu, s3a, o);
    }
    const int w = tid >> 5;
    if ((tid & 31) == 0) shp[w] = make_float4(s0, s1a, s2a, s3a);
    __syncthreads();

    if (tid == 0) {
        float4 acc = shp[0];
        #pragma unroll
        for (int k = 1; k < NTHR / 32; k++) {
            acc.x += shp[k].x; acc.y += shp[k].y;
            acc.z += shp[k].z; acc.w += shp[k].w;
        }
        g_part[blockIdx.x] = acc;
    }
}

#define FTHR 1024

__global__ __launch_bounds__(FTHR) void attnloss_final_kernel(float* __restrict__ out)
{
    float4 acc = make_float4(0.f, 0.f, 0.f, 0.f);
    // 4096 partials / 1024 threads = 4 each; fully unrolled for MLP.
    #pragma unroll
    for (int u = 0; u < NCTA / FTHR; u++) {
        const float4 p = g_part[u * FTHR + threadIdx.x];
        acc.x += p.x; acc.y += p.y; acc.z += p.z; acc.w += p.w;
    }
    #pragma unroll
    for (int o = 16; o > 0; o >>= 1) {
        acc.x += __shfl_down_sync(0xffffffffu, acc.x, o);
        acc.y += __shfl_down_sync(0xffffffffu, acc.y, o);
        acc.z += __shfl_down_sync(0xffffffffu, acc.z, o);
        acc.w += __shfl_down_sync(0xffffffffu, acc.w, o);
    }
    __shared__ float4 shp[FTHR / 32];
    const int w = threadIdx.x >> 5;
    if ((threadIdx.x & 31) == 0) shp[w] = acc;
    __syncthreads();

    if (threadIdx.x == 0) {
        float4 r = shp[0];
        #pragma unroll
        for (int k = 1; k < FTHR / 32; k++) {
            r.x += shp[k].x; r.y += shp[k].y;
            r.z += shp[k].z; r.w += shp[k].w;
        }
        const float inv = 1.0f / (float)TOTAL_ELEMS;
        const float pos = r.x * inv;
        const float n1  = r.y * inv;
        const float n2  = r.z * inv;
        const float n3  = r.w * inv;
        // TEMP = 1:  loss = -pos + log(exp(n1)+exp(n2)+exp(n3))
        out[0] = -pos + logf(expf(n1) + expf(n2) + expf(n3));
    }
}

extern "C" void kernel_launch(void* const* d_in, const int* in_sizes, int n_in,
                              void* d_out, int out_size)
{
    const float* x     = (const float*)d_in[0];
    const float* attn  = (const float*)d_in[1];
    const float* noise = (const float*)d_in[2];
    const int*   mask  = (const int*)d_in[3];
    const int* pB1 = (const int*)d_in[4];
    const int* pT1 = (const int*)d_in[5];
    const int* pC1 = (const int*)d_in[6];
    const int* pP1 = (const int*)d_in[7];
    const int* pB2 = (const int*)d_in[8];
    const int* pT2 = (const int*)d_in[9];
    const int* pC2 = (const int*)d_in[10];
    const int* pP2 = (const int*)d_in[11];
    const int* pB3 = (const int*)d_in[12];
    const int* pT3 = (const int*)d_in[13];
    const int* pC3 = (const int*)d_in[14];
    const int* pP3 = (const int*)d_in[15];

    // Unconditional every call: no static guards, idempotent, capture-safe.
    cudaFuncSetAttribute(attnloss_partial_kernel,
                         cudaFuncAttributeMaxDynamicSharedMemorySize, SMEM_TOTAL);

    attnloss_partial_kernel<<<NCTA, NTHR, SMEM_TOTAL>>>(
        x, attn, noise, mask,
        pB1, pT1, pC1, pP1,
        pB2, pT2, pC2, pP2,
        pB3, pT3, pC3, pP3);
    attnloss_final_kernel<<<1, FTHR>>>((float*)d_out);
}

// round 15
// speedup vs baseline: 1.0667x; 1.0317x over previous
#include <cuda_runtime.h>
#include <cstdint>

#define B_DIM 16
#define T_DIM 8
#define C_DIM 64
#define P_DIM 2048
#define ROWS  (B_DIM * T_DIM * C_DIM)     // 8192 destination rows
#define TOTAL_ELEMS (ROWS * P_DIM)        // 16777216
#define NTHR 256
#define ROW_BYTES (P_DIM * 4)             // 8192 bytes per row

// Block partials (float4 per destination row). No device-side allocation.
__device__ float4 g_part[ROWS];

__device__ __forceinline__ uint32_t smem_u32(const void* p) {
    uint32_t a;
    asm("{ .reg .u64 t; cvta.to.shared.u64 t, %1; cvt.u32.u64 %0, t; }"
        : "=r"(a) : "l"(p));
    return a;
}

// Exact R6 structure (best measured main: ~52.8us): one CTA per destination
// row, TMA row-fill, ALL loads batched up front for max MLP. Plus a PDL
// launch_dependents signal after the partial store.
__global__ __launch_bounds__(NTHR) void attnloss_partial_kernel(
    const float* __restrict__ x,
    const float* __restrict__ attn,
    const float* __restrict__ noise,
    const int* __restrict__ mask,    // bool promoted to 4-byte words
    const int* __restrict__ pB1, const int* __restrict__ pT1,
    const int* __restrict__ pC1, const int* __restrict__ pP1,
    const int* __restrict__ pB2, const int* __restrict__ pT2,
    const int* __restrict__ pC2, const int* __restrict__ pP2,
    const int* __restrict__ pB3, const int* __restrict__ pT3,
    const int* __restrict__ pC3, const int* __restrict__ pP3)
{
    __shared__ __align__(128) float sm[3 * P_DIM];   // 24 KB: three source rows
    __shared__ __align__(8) uint64_t mbar;

    const float* const sm1 = sm;
    const float* const sm2 = sm + P_DIM;
    const float* const sm3 = sm + 2 * P_DIM;

    const int tid = threadIdx.x;
    const int blk = blockIdx.x;              // destination row id
    const uint32_t mbar_a = smem_u32(&mbar);

    if (tid == 0) {
        asm volatile("mbarrier.init.shared.b64 [%0], 1;" :: "r"(mbar_a) : "memory");
    }
    __syncthreads();

    if (tid == 0) {
        const int c = blk & (C_DIM - 1);
        const int t = (blk >> 6) & (T_DIM - 1);
        const int b = blk >> 9;
        // Source row bases (contiguous 8 KB rows of x). 32-bit math: max < 2^24.
        const int rb1 = ((((__ldg(pB1 + b) << 3) + __ldg(pT1 + t)) << 6) + __ldg(pC1 + c)) << 11;
        const int rb2 = ((((__ldg(pB2 + b) << 3) + __ldg(pT2 + t)) << 6) + __ldg(pC2 + c)) << 11;
        const int rb3 = ((((__ldg(pB3 + b) << 3) + __ldg(pT3 + t)) << 6) + __ldg(pC3 + c)) << 11;

        asm volatile("mbarrier.arrive.expect_tx.shared.b64 _, [%0], %1;"
                     :: "r"(mbar_a), "r"(3 * ROW_BYTES) : "memory");
        asm volatile("cp.async.bulk.shared::cta.global.mbarrier::complete_tx::bytes [%0], [%1], %2, [%3];"
                     :: "r"(smem_u32(sm1)), "l"(x + rb1), "r"(ROW_BYTES), "r"(mbar_a) : "memory");
        asm volatile("cp.async.bulk.shared::cta.global.mbarrier::complete_tx::bytes [%0], [%1], %2, [%3];"
                     :: "r"(smem_u32(sm2)), "l"(x + rb2), "r"(ROW_BYTES), "r"(mbar_a) : "memory");
        asm volatile("cp.async.bulk.shared::cta.global.mbarrier::complete_tx::bytes [%0], [%1], %2, [%3];"
                     :: "r"(smem_u32(sm3)), "l"(x + rb3), "r"(ROW_BYTES), "r"(mbar_a) : "memory");
    }

    // Batch ALL streaming loads up front (max MLP, in flight across the wait).
    float4 x4[2], a4[2], n4[2];
    int4 m4[2], pp1[2], pp2[2], pp3[2];
    #pragma unroll
    for (int j = 0; j < 2; j++) {
        const int vloc = j * NTHR + tid;         // 0..511, warp-contiguous
        const int gv = (blk << 9) + vloc;
        x4[j] = __ldg((const float4*)x + gv);            // L2-resident
        a4[j] = __ldcs((const float4*)attn + gv);        // stream
        n4[j] = __ldcs((const float4*)noise + gv);       // stream
        m4[j] = __ldcs((const int4*)mask + gv);          // stream
        pp1[j] = __ldg((const int4*)pP1 + vloc);         // L1-hot tables
        pp2[j] = __ldg((const int4*)pP2 + vloc);
        pp3[j] = __ldg((const int4*)pP3 + vloc);
    }

    // Wait for the three source rows (acquire orders the LDS gathers below).
    {
        uint32_t done;
        asm volatile(
            "{\n\t.reg .pred p;\n\t"
            "mbarrier.try_wait.parity.acquire.cta.shared::cta.b64 p, [%1], 0;\n\t"
            "selp.b32 %0, 1, 0, p;\n\t}"
            : "=r"(done) : "r"(mbar_a) : "memory");
        if (!done) {
            asm volatile(
                "{\n\t.reg .pred P1;\n\t"
                "WAIT_LOOP_%=:\n\t"
                "mbarrier.try_wait.parity.acquire.cta.shared::cta.b64 P1, [%0], 0, 0x989680;\n\t"
                "@P1 bra.uni WAIT_DONE_%=;\n\t"
                "bra.uni WAIT_LOOP_%=;\n\t"
                "WAIT_DONE_%=:\n\t}"
                :: "r"(mbar_a) : "memory");
        }
    }

    float s0 = 0.f, s1a = 0.f, s2a = 0.f, s3a = 0.f;

    #pragma unroll
    for (int j = 0; j < 2; j++) {
        s0 += (m4[j].x ? a4[j].x * n4[j].x * n4[j].x : 0.f)
            + (m4[j].y ? a4[j].y * n4[j].y * n4[j].y : 0.f)
            + (m4[j].z ? a4[j].z * n4[j].z * n4[j].z : 0.f)
            + (m4[j].w ? a4[j].w * n4[j].w * n4[j].w : 0.f);

        float d;
        d = x4[j].x - sm1[pp1[j].x]; s1a += a4[j].x * d * d;
        d = x4[j].y - sm1[pp1[j].y]; s1a += a4[j].y * d * d;
        d = x4[j].z - sm1[pp1[j].z]; s1a += a4[j].z * d * d;
        d = x4[j].w - sm1[pp1[j].w]; s1a += a4[j].w * d * d;

        d = x4[j].x - sm2[pp2[j].x]; s2a += a4[j].x * d * d;
        d = x4[j].y - sm2[pp2[j].y]; s2a += a4[j].y * d * d;
        d = x4[j].z - sm2[pp2[j].z]; s2a += a4[j].z * d * d;
        d = x4[j].w - sm2[pp2[j].w]; s2a += a4[j].w * d * d;

        d = x4[j].x - sm3[pp3[j].x]; s3a += a4[j].x * d * d;
        d = x4[j].y - sm3[pp3[j].y]; s3a += a4[j].y * d * d;
        d = x4[j].z - sm3[pp3[j].z]; s3a += a4[j].z * d * d;
        d = x4[j].w - sm3[pp3[j].w]; s3a += a4[j].w * d * d;
    }

    // Block reduction (deterministic tree)
    #pragma unroll
    for (int o = 16; o > 0; o >>= 1) {
        s0  += __shfl_down_sync(0xffffffffu, s0,  o);
        s1a += __shfl_down_sync(0xffffffffu, s1a, o);
        s2a += __shfl_down_sync(0xffffffffu, s2a, o);
        s3a += __shfl_down_sync(0xffffffffu, s3a, o);
    }
    __shared__ float4 shp[NTHR / 32];
    const int w = tid >> 5;
    if ((tid & 31) == 0) shp[w] = make_float4(s0, s1a, s2a, s3a);
    __syncthreads();

    if (tid == 0) {
        float4 acc = shp[0];
        #pragma unroll
        for (int k = 1; k < NTHR / 32; k++) {
            acc.x += shp[k].x; acc.y += shp[k].y;
            acc.z += shp[k].z; acc.w += shp[k].w;
        }
        g_part[blk] = acc;
    }

    // PDL: this CTA's output is written; allow the dependent (final) kernel
    // to begin launching. Visibility is guaranteed by griddepcontrol.wait
    // in the dependent.
    asm volatile("griddepcontrol.launch_dependents;");
}

#define FTHR 1024

__global__ __launch_bounds__(FTHR) void attnloss_final_kernel(float* __restrict__ out)
{
    // PDL: wait until all primary CTAs' writes (g_part) are visible.
    asm volatile("griddepcontrol.wait;");

    float4 acc = make_float4(0.f, 0.f, 0.f, 0.f);
    #pragma unroll
    for (int u = 0; u < ROWS / FTHR; u++) {
        const float4 p = g_part[u * FTHR + threadIdx.x];
        acc.x += p.x; acc.y += p.y; acc.z += p.z; acc.w += p.w;
    }
    #pragma unroll
    for (int o = 16; o > 0; o >>= 1) {
        acc.x += __shfl_down_sync(0xffffffffu, acc.x, o);
        acc.y += __shfl_down_sync(0xffffffffu, acc.y, o);
        acc.z += __shfl_down_sync(0xffffffffu, acc.z, o);
        acc.w += __shfl_down_sync(0xffffffffu, acc.w, o);
    }
    __shared__ float4 shp[FTHR / 32];
    const int w = threadIdx.x >> 5;
    if ((threadIdx.x & 31) == 0) shp[w] = acc;
    __syncthreads();

    if (threadIdx.x == 0) {
        float4 r = shp[0];
        #pragma unroll
        for (int k = 1; k < FTHR / 32; k++) {
            r.x += shp[k].x; r.y += shp[k].y;
            r.z += shp[k].z; r.w += shp[k].w;
        }
        const float inv = 1.0f / (float)TOTAL_ELEMS;
        const float pos = r.x * inv;
        const float n1  = r.y * inv;
        const float n2  = r.z * inv;
        const float n3  = r.w * inv;
        // TEMP = 1:  loss = -pos + log(exp(n1)+exp(n2)+exp(n3))
        out[0] = -pos + logf(expf(n1) + expf(n2) + expf(n3));
    }
}

extern "C" void kernel_launch(void* const* d_in, const int* in_sizes, int n_in,
                              void* d_out, int out_size)
{
    const float* x     = (const float*)d_in[0];
    const float* attn  = (const float*)d_in[1];
    const float* noise = (const float*)d_in[2];
    const int*   mask  = (const int*)d_in[3];
    const int* pB1 = (const int*)d_in[4];
    const int* pT1 = (const int*)d_in[5];
    const int* pC1 = (const int*)d_in[6];
    const int* pP1 = (const int*)d_in[7];
    const int* pB2 = (const int*)d_in[8];
    const int* pT2 = (const int*)d_in[9];
    const int* pC2 = (const int*)d_in[10];
    const int* pP2 = (const int*)d_in[11];
    const int* pB3 = (const int*)d_in[12];
    const int* pT3 = (const int*)d_in[13];
    const int* pC3 = (const int*)d_in[14];
    const int* pP3 = (const int*)d_in[15];

    attnloss_partial_kernel<<<ROWS, NTHR>>>(
        x, attn, noise, mask,
        pB1, pT1, pC1, pP1,
        pB2, pT2, pC2, pP2,
        pB3, pT3, pC3, pP3);

    // Final kernel with Programmatic Dependent Launch: overlaps its launch
    // and setup with the partial kernel's tail; griddepcontrol.wait inside
    // provides the dependency + memory visibility.
    {
        cudaLaunchConfig_t cfg = {};
        cfg.gridDim  = dim3(1, 1, 1);
        cfg.blockDim = dim3(FTHR, 1, 1);
        cfg.dynamicSmemBytes = 0;
        cudaLaunchAttribute attrs[1];
        attrs[0].id = cudaLaunchAttributeProgrammaticStreamSerialization;
        attrs[0].val.programmaticStreamSerializationAllowed = 1;
        cfg.attrs = attrs;
        cfg.numAttrs = 1;
        cudaLaunchKernelEx(&cfg, attnloss_final_kernel, (float*)d_out);
    }
}

// round 16
// speedup vs baseline: 1.0684x; 1.0016x over previous
#include <cuda_runtime.h>
#include <cstdint>

#define B_DIM 16
#define T_DIM 8
#define C_DIM 64
#define P_DIM 2048
#define ROWS  (B_DIM * T_DIM * C_DIM)     // 8192 destination rows
#define TOTAL_ELEMS (ROWS * P_DIM)        // 16777216
#define NTHR 256
#define ROW_BYTES (P_DIM * 4)             // 8192 bytes per row
#define FBLK 32                           // final-stage CTAs

// Partials + second-stage partials + completion counter. No allocations.
__device__ float4 g_part[ROWS];
__device__ float4 g_part2[FBLK];
__device__ unsigned int g_cnt = 0;

__device__ __forceinline__ uint32_t smem_u32(const void* p) {
    uint32_t a;
    asm("{ .reg .u64 t; cvta.to.shared.u64 t, %1; cvt.u32.u64 %0, t; }"
        : "=r"(a) : "l"(p));
    return a;
}

// Exact R6 main (best measured: ~52.8us): one CTA per destination row,
// TMA row-fill, ALL loads batched up front for max MLP. PDL signal at end.
__global__ __launch_bounds__(NTHR) void attnloss_partial_kernel(
    const float* __restrict__ x,
    const float* __restrict__ attn,
    const float* __restrict__ noise,
    const int* __restrict__ mask,    // bool promoted to 4-byte words
    const int* __restrict__ pB1, const int* __restrict__ pT1,
    const int* __restrict__ pC1, const int* __restrict__ pP1,
    const int* __restrict__ pB2, const int* __restrict__ pT2,
    const int* __restrict__ pC2, const int* __restrict__ pP2,
    const int* __restrict__ pB3, const int* __restrict__ pT3,
    const int* __restrict__ pC3, const int* __restrict__ pP3)
{
    __shared__ __align__(128) float sm[3 * P_DIM];   // 24 KB: three source rows
    __shared__ __align__(8) uint64_t mbar;

    const float* const sm1 = sm;
    const float* const sm2 = sm + P_DIM;
    const float* const sm3 = sm + 2 * P_DIM;

    const int tid = threadIdx.x;
    const int blk = blockIdx.x;              // destination row id
    const uint32_t mbar_a = smem_u32(&mbar);

    if (tid == 0) {
        asm volatile("mbarrier.init.shared.b64 [%0], 1;" :: "r"(mbar_a) : "memory");
    }
    __syncthreads();

    if (tid == 0) {
        const int c = blk & (C_DIM - 1);
        const int t = (blk >> 6) & (T_DIM - 1);
        const int b = blk >> 9;
        const int rb1 = ((((__ldg(pB1 + b) << 3) + __ldg(pT1 + t)) << 6) + __ldg(pC1 + c)) << 11;
        const int rb2 = ((((__ldg(pB2 + b) << 3) + __ldg(pT2 + t)) << 6) + __ldg(pC2 + c)) << 11;
        const int rb3 = ((((__ldg(pB3 + b) << 3) + __ldg(pT3 + t)) << 6) + __ldg(pC3 + c)) << 11;

        asm volatile("mbarrier.arrive.expect_tx.shared.b64 _, [%0], %1;"
                     :: "r"(mbar_a), "r"(3 * ROW_BYTES) : "memory");
        asm volatile("cp.async.bulk.shared::cta.global.mbarrier::complete_tx::bytes [%0], [%1], %2, [%3];"
                     :: "r"(smem_u32(sm1)), "l"(x + rb1), "r"(ROW_BYTES), "r"(mbar_a) : "memory");
        asm volatile("cp.async.bulk.shared::cta.global.mbarrier::complete_tx::bytes [%0], [%1], %2, [%3];"
                     :: "r"(smem_u32(sm2)), "l"(x + rb2), "r"(ROW_BYTES), "r"(mbar_a) : "memory");
        asm volatile("cp.async.bulk.shared::cta.global.mbarrier::complete_tx::bytes [%0], [%1], %2, [%3];"
                     :: "r"(smem_u32(sm3)), "l"(x + rb3), "r"(ROW_BYTES), "r"(mbar_a) : "memory");
    }

    // Batch ALL streaming loads up front (max MLP, in flight across the wait).
    float4 x4[2], a4[2], n4[2];
    int4 m4[2], pp1[2], pp2[2], pp3[2];
    #pragma unroll
    for (int j = 0; j < 2; j++) {
        const int vloc = j * NTHR + tid;         // 0..511, warp-contiguous
        const int gv = (blk << 9) + vloc;
        x4[j] = __ldg((const float4*)x + gv);            // L2-resident
        a4[j] = __ldcs((const float4*)attn + gv);        // stream
        n4[j] = __ldcs((const float4*)noise + gv);       // stream
        m4[j] = __ldcs((const int4*)mask + gv);          // stream
        pp1[j] = __ldg((const int4*)pP1 + vloc);         // L1-hot tables
        pp2[j] = __ldg((const int4*)pP2 + vloc);
        pp3[j] = __ldg((const int4*)pP3 + vloc);
    }

    // Wait for the three source rows (acquire orders the LDS gathers below).
    {
        uint32_t done;
        asm volatile(
            "{\n\t.reg .pred p;\n\t"
            "mbarrier.try_wait.parity.acquire.cta.shared::cta.b64 p, [%1], 0;\n\t"
            "selp.b32 %0, 1, 0, p;\n\t}"
            : "=r"(done) : "r"(mbar_a) : "memory");
        if (!done) {
            asm volatile(
                "{\n\t.reg .pred P1;\n\t"
                "WAIT_LOOP_%=:\n\t"
                "mbarrier.try_wait.parity.acquire.cta.shared::cta.b64 P1, [%0], 0, 0x989680;\n\t"
                "@P1 bra.uni WAIT_DONE_%=;\n\t"
                "bra.uni WAIT_LOOP_%=;\n\t"
                "WAIT_DONE_%=:\n\t}"
                :: "r"(mbar_a) : "memory");
        }
    }

    float s0 = 0.f, s1a = 0.f, s2a = 0.f, s3a = 0.f;

    #pragma unroll
    for (int j = 0; j < 2; j++) {
        s0 += (m4[j].x ? a4[j].x * n4[j].x * n4[j].x : 0.f)
            + (m4[j].y ? a4[j].y * n4[j].y * n4[j].y : 0.f)
            + (m4[j].z ? a4[j].z * n4[j].z * n4[j].z : 0.f)
            + (m4[j].w ? a4[j].w * n4[j].w * n4[j].w : 0.f);

        float d;
        d = x4[j].x - sm1[pp1[j].x]; s1a += a4[j].x * d * d;
        d = x4[j].y - sm1[pp1[j].y]; s1a += a4[j].y * d * d;
        d = x4[j].z - sm1[pp1[j].z]; s1a += a4[j].z * d * d;
        d = x4[j].w - sm1[pp1[j].w]; s1a += a4[j].w * d * d;

        d = x4[j].x - sm2[pp2[j].x]; s2a += a4[j].x * d * d;
        d = x4[j].y - sm2[pp2[j].y]; s2a += a4[j].y * d * d;
        d = x4[j].z - sm2[pp2[j].z]; s2a += a4[j].z * d * d;
        d = x4[j].w - sm2[pp2[j].w]; s2a += a4[j].w * d * d;

        d = x4[j].x - sm3[pp3[j].x]; s3a += a4[j].x * d * d;
        d = x4[j].y - sm3[pp3[j].y]; s3a += a4[j].y * d * d;
        d = x4[j].z - sm3[pp3[j].z]; s3a += a4[j].z * d * d;
        d = x4[j].w - sm3[pp3[j].w]; s3a += a4[j].w * d * d;
    }

    // Block reduction (deterministic tree)
    #pragma unroll
    for (int o = 16; o > 0; o >>= 1) {
        s0  += __shfl_down_sync(0xffffffffu, s0,  o);
        s1a += __shfl_down_sync(0xffffffffu, s1a, o);
        s2a += __shfl_down_sync(0xffffffffu, s2a, o);
        s3a += __shfl_down_sync(0xffffffffu, s3a, o);
    }
    __shared__ float4 shp[NTHR / 32];
    const int w = tid >> 5;
    if ((tid & 31) == 0) shp[w] = make_float4(s0, s1a, s2a, s3a);
    __syncthreads();

    if (tid == 0) {
        float4 acc = shp[0];
        #pragma unroll
        for (int k = 1; k < NTHR / 32; k++) {
            acc.x += shp[k].x; acc.y += shp[k].y;
            acc.z += shp[k].z; acc.w += shp[k].w;
        }
        g_part[blk] = acc;
    }

    asm volatile("griddepcontrol.launch_dependents;");
}

// Final stage: 32 CTAs reduce 256 partials each (coalesced, spread over 32
// SMs), then the last-arriving CTA reduces the 32 second-stage partials.
__global__ __launch_bounds__(NTHR) void attnloss_final_kernel(float* __restrict__ out)
{
    asm volatile("griddepcontrol.wait;");

    const int tid = threadIdx.x;
    const int blk = blockIdx.x;

    const float4 p = g_part[(blk << 8) + tid];   // one float4 per thread
    float s0 = p.x, s1 = p.y, s2 = p.z, s3 = p.w;

    #pragma unroll
    for (int o = 16; o > 0; o >>= 1) {
        s0 += __shfl_down_sync(0xffffffffu, s0, o);
        s1 += __shfl_down_sync(0xffffffffu, s1, o);
        s2 += __shfl_down_sync(0xffffffffu, s2, o);
        s3 += __shfl_down_sync(0xffffffffu, s3, o);
    }
    __shared__ float4 shp[NTHR / 32];
    const int w = tid >> 5;
    if ((tid & 31) == 0) shp[w] = make_float4(s0, s1, s2, s3);
    __syncthreads();

    if (tid == 0) {
        float4 acc = shp[0];
        #pragma unroll
        for (int k = 1; k < NTHR / 32; k++) {
            acc.x += shp[k].x; acc.y += shp[k].y;
            acc.z += shp[k].z; acc.w += shp[k].w;
        }
        g_part2[blk] = acc;
    }

    // Last-block pattern: writer side fences, reader side uses L2 loads.
    __shared__ bool isLast;
    __threadfence();
    if (tid == 0)
        isLast = (atomicAdd(&g_cnt, 1u) == (unsigned)(FBLK - 1));
    __syncthreads();

    if (isLast && tid < 32) {
        const float4 q = __ldcg(&g_part2[tid]);   // L2 path (cross-SM coherent)
        float r0 = q.x, r1 = q.y, r2 = q.z, r3 = q.w;
        #pragma unroll
        for (int o = 16; o > 0; o >>= 1) {
            r0 += __shfl_down_sync(0xffffffffu, r0, o);
            r1 += __shfl_down_sync(0xffffffffu, r1, o);
            r2 += __shfl_down_sync(0xffffffffu, r2, o);
            r3 += __shfl_down_sync(0xffffffffu, r3, o);
        }
        if (tid == 0) {
            const float inv = 1.0f / (float)TOTAL_ELEMS;
            const float pos = r0 * inv;
            const float n1  = r1 * inv;
            const float n2  = r2 * inv;
            const float n3  = r3 * inv;
            // TEMP = 1:  loss = -pos + log(exp(n1)+exp(n2)+exp(n3))
            out[0] = -pos + logf(expf(n1) + expf(n2) + expf(n3));
            g_cnt = 0;   // reset for next graph replay
        }
    }
}

extern "C" void kernel_launch(void* const* d_in, const int* in_sizes, int n_in,
                              void* d_out, int out_size)
{
    const float* x     = (const float*)d_in[0];
    const float* attn  = (const float*)d_in[1];
    const float* noise = (const float*)d_in[2];
    const int*   mask  = (const int*)d_in[3];
    const int* pB1 = (const int*)d_in[4];
    const int* pT1 = (const int*)d_in[5];
    const int* pC1 = (const int*)d_in[6];
    const int* pP1 = (const int*)d_in[7];
    const int* pB2 = (const int*)d_in[8];
    const int* pT2 = (const int*)d_in[9];
    const int* pC2 = (const int*)d_in[10];
    const int* pP2 = (const int*)d_in[11];
    const int* pB3 = (const int*)d_in[12];
    const int* pT3 = (const int*)d_in[13];
    const int* pC3 = (const int*)d_in[14];
    const int* pP3 = (const int*)d_in[15];

    attnloss_partial_kernel<<<ROWS, NTHR>>>(
        x, attn, noise, mask,
        pB1, pT1, pC1, pP1,
        pB2, pT2, pC2, pP2,
        pB3, pT3, pC3, pP3);

    // Final stage with PDL: overlaps launch with the partial kernel's tail.
    {
        cudaLaunchConfig_t cfg = {};
        cfg.gridDim  = dim3(FBLK, 1, 1);
        cfg.blockDim = dim3(NTHR, 1, 1);
        cfg.dynamicSmemBytes = 0;
        cudaLaunchAttribute attrs[1];
        attrs[0].id = cudaLaunchAttributeProgrammaticStreamSerialization;
        attrs[0].val.programmaticStreamSerializationAllowed = 1;
        cfg.attrs = attrs;
        cfg.numAttrs = 1;
        cudaLaunchKernelEx(&cfg, attnloss_final_kernel, (float*)d_out);
    }
}